// round 1
// baseline (speedup 1.0000x reference)
#include <cuda_runtime.h>
#include <cuda_bf16.h>
#include <math.h>

#define NTRAJ  256
#define NTP    512
#define LATENT 256
#define INPUT  128
#define NUNITS 256
#define GIN    (LATENT + INPUT)   // 384
#define DEC_OUT 128
#define NSTEP  (NTP - 1)          // 511

#define G     4                   // trajectories per block
#define NBLK  (NTRAJ / G)         // 64 blocks

__device__ __forceinline__ float sigmoidf_(float x) { return 1.f / (1.f + expf(-x)); }

// out[g][j] (j in [0,256)) accumulators: acc[g] = b[j] + sum_k sin[g][k] * W[k*256+j]
// One weight LDG feeds G FMAs; activations read as float4 broadcasts from shared.
template <int K>
__device__ __forceinline__ void gemv256(float acc[G], const float* __restrict__ W,
                                        const float* __restrict__ b,
                                        const float* sin, int sstride, int j) {
#pragma unroll
    for (int g = 0; g < G; g++) acc[g] = b[j];
#pragma unroll 2
    for (int k = 0; k < K; k += 4) {
        float w0 = W[(k + 0) * 256 + j];
        float w1 = W[(k + 1) * 256 + j];
        float w2 = W[(k + 2) * 256 + j];
        float w3 = W[(k + 3) * 256 + j];
#pragma unroll
        for (int g = 0; g < G; g++) {
            float4 a = *(const float4*)(sin + g * sstride + k);
            acc[g] = fmaf(a.x, w0, acc[g]);
            acc[g] = fmaf(a.y, w1, acc[g]);
            acc[g] = fmaf(a.z, w2, acc[g]);
            acc[g] = fmaf(a.w, w3, acc[g]);
        }
    }
}

__global__ __launch_bounds__(256, 1)
void rnn_decay_kernel(
    const float* __restrict__ data, const float* __restrict__ ts,
    const float* __restrict__ ug_w1,  const float* __restrict__ ug_b1,
    const float* __restrict__ ug_w2,  const float* __restrict__ ug_b2,
    const float* __restrict__ ugt_w1, const float* __restrict__ ugt_b1,
    const float* __restrict__ ugt_w2, const float* __restrict__ ugt_b2,
    const float* __restrict__ rg_w1,  const float* __restrict__ rg_b1,
    const float* __restrict__ rg_w2,  const float* __restrict__ rg_b2,
    const float* __restrict__ ns_w1,  const float* __restrict__ ns_b1,
    const float* __restrict__ ns_w2,  const float* __restrict__ ns_b2,
    const float* __restrict__ dk_w1,  const float* __restrict__ dk_b1,
    const float* __restrict__ dk_w2,  const float* __restrict__ dk_b2,
    const float* __restrict__ dec_w,  const float* __restrict__ dec_b,
    float* __restrict__ out)
{
    __shared__ __align__(16) float sy [G * LATENT];   // y state (becomes y_end after decay)
    __shared__ __align__(16) float syt[G * LATENT];   // yt state
    __shared__ __align__(16) float syc[G * GIN];      // [y_end | xh] gate input
    __shared__ __align__(16) float sh [G * NUNITS];   // hidden / mean_ydec scratch
    __shared__ float sdt[G], sdecay[G], smask[G];
    __shared__ float sred[8][G];

    const int j    = threadIdx.x;       // output unit 0..255
    const int tb   = blockIdx.x * G;    // first trajectory of this block
    const int lane = j & 31, warp = j >> 5;

    float* out_prev = out;                                           // (1,256,256)
    float* out_vol  = out + (size_t)NTRAJ * LATENT;                  // (256,511,128)
    float* out_dts  = out + (size_t)NTRAJ * LATENT + (size_t)NTRAJ * NSTEP * DEC_OUT;  // (256,511)

#pragma unroll
    for (int g = 0; g < G; g++) { sy[g * LATENT + j] = 0.f; syt[g * LATENT + j] = 0.f; }

    for (int t = 0; t < NTP; t++) {
        __syncthreads();   // previous-iter readers of sy/syt/syc/sh are done

        // ---- load xh into yc tail, compute per-traj mask, dt ----
        if (j < INPUT) {
#pragma unroll
            for (int g = 0; g < G; g++)
                syc[g * GIN + LATENT + j] =
                    data[((size_t)(tb + g) * NTP + t) * (2 * INPUT) + j];
        }
        if (warp < G) {   // warp g computes mask for trajectory g
            const float* xp = data + ((size_t)(tb + warp) * NTP + t) * (2 * INPUT) + INPUT;
            float s = xp[lane] + xp[lane + 32] + xp[lane + 64] + xp[lane + 96];
#pragma unroll
            for (int off = 16; off; off >>= 1) s += __shfl_xor_sync(0xffffffffu, s, off);
            if (lane == 0) smask[warp] = (s > 0.f) ? 1.f : 0.f;
        }
        if (j < G && t > 0) {
            float d = ts[(size_t)(tb + j) * NTP + t] - ts[(size_t)(tb + j) * NTP + t - 1];
            sdt[j] = d;
            out_dts[(size_t)(tb + j) * NSTEP + (t - 1)] = d;
        }
        __syncthreads();

        float acc[G];

        if (t > 0) {
            // ---- decay MLP: relu(relu(y @ dk_w1 + b1) @ dk_w2 + b2) ----
            gemv256<LATENT>(acc, dk_w1, dk_b1, sy, LATENT, j);
#pragma unroll
            for (int g = 0; g < G; g++) sh[g * NUNITS + j] = fmaxf(acc[g], 0.f);
            __syncthreads();
            {
                float v[G];
                float w2v = dk_w2[j];
#pragma unroll
                for (int g = 0; g < G; g++) v[g] = sh[g * NUNITS + j] * w2v;
#pragma unroll
                for (int off = 16; off; off >>= 1) {
#pragma unroll
                    for (int g = 0; g < G; g++) v[g] += __shfl_xor_sync(0xffffffffu, v[g], off);
                }
                if (lane == 0) {
#pragma unroll
                    for (int g = 0; g < G; g++) sred[warp][g] = v[g];
                }
            }
            __syncthreads();
            if (j < G) {
                float s = dk_b2[0];
#pragma unroll
                for (int w = 0; w < 8; w++) s += sred[w][j];
                sdecay[j] = fmaxf(s, 0.f);
            }
            __syncthreads();

            // ---- elementwise: mean_ydec (interp pts 0,0.5), y_end (interp pt 1) ----
#pragma unroll
            for (int g = 0; g < G; g++) {
                float d  = sdecay[g] * sdt[g];
                float e1 = expf(-0.5f * d);
                float e2 = expf(-d);
                float yv = sy[g * LATENT + j], ytv = syt[g * LATENT + j];
                float df = yv - ytv;
                sh[g * NUNITS + j] = ytv + df * (0.5f * (1.f + e1));  // mean(ydec[0..1])
                float yend = ytv + df * e2;
                sy[g * LATENT + j] = yend;
                syc[g * GIN + j]   = yend;
            }
            __syncthreads();

            // ---- vol = mean_ydec @ dec_w + dec_b  (128 outputs) ----
            if (j < DEC_OUT) {
                float va[G];
#pragma unroll
                for (int g = 0; g < G; g++) va[g] = dec_b[j];
#pragma unroll 2
                for (int k = 0; k < LATENT; k += 4) {
                    float w0 = dec_w[(k + 0) * DEC_OUT + j];
                    float w1 = dec_w[(k + 1) * DEC_OUT + j];
                    float w2 = dec_w[(k + 2) * DEC_OUT + j];
                    float w3 = dec_w[(k + 3) * DEC_OUT + j];
#pragma unroll
                    for (int g = 0; g < G; g++) {
                        float4 a = *(const float4*)(sh + g * NUNITS + k);
                        va[g] = fmaf(a.x, w0, fmaf(a.y, w1, fmaf(a.z, w2, fmaf(a.w, w3, va[g]))));
                    }
                }
#pragma unroll
                for (int g = 0; g < G; g++)
                    out_vol[((size_t)(tb + g) * NSTEP + (t - 1)) * DEC_OUT + j] = va[g];
            }
            __syncthreads();   // sh is reused by gates below
        } else {
            // t == 0: gru_step(y0=0, yt0=0, x0)
#pragma unroll
            for (int g = 0; g < G; g++) syc[g * GIN + j] = 0.f;
            __syncthreads();
        }

        // ---- GRU gates ----
        float u[G], ut[G];

        // u = sigmoid(tanh(yc@ug_w1+b1)@ug_w2+b2)
        gemv256<GIN>(acc, ug_w1, ug_b1, syc, GIN, j);
#pragma unroll
        for (int g = 0; g < G; g++) sh[g * NUNITS + j] = tanhf(acc[g]);
        __syncthreads();
        gemv256<NUNITS>(acc, ug_w2, ug_b2, sh, NUNITS, j);
#pragma unroll
        for (int g = 0; g < G; g++) u[g] = sigmoidf_(acc[g]);
        __syncthreads();

        // ut
        gemv256<GIN>(acc, ugt_w1, ugt_b1, syc, GIN, j);
#pragma unroll
        for (int g = 0; g < G; g++) sh[g * NUNITS + j] = tanhf(acc[g]);
        __syncthreads();
        gemv256<NUNITS>(acc, ugt_w2, ugt_b2, sh, NUNITS, j);
#pragma unroll
        for (int g = 0; g < G; g++) ut[g] = sigmoidf_(acc[g]);
        __syncthreads();

        // r (folded directly into yc head: yc[:256] *= r)
        gemv256<GIN>(acc, rg_w1, rg_b1, syc, GIN, j);
#pragma unroll
        for (int g = 0; g < G; g++) sh[g * NUNITS + j] = tanhf(acc[g]);
        __syncthreads();
        gemv256<NUNITS>(acc, rg_w2, rg_b2, sh, NUNITS, j);
#pragma unroll
        for (int g = 0; g < G; g++) syc[g * GIN + j] *= sigmoidf_(acc[g]);
        __syncthreads();

        // new_state = tanh([y*r | xh]@ns_w1+b1)@ns_w2+b2  (linear output)
        gemv256<GIN>(acc, ns_w1, ns_b1, syc, GIN, j);
#pragma unroll
        for (int g = 0; g < G; g++) sh[g * NUNITS + j] = tanhf(acc[g]);
        __syncthreads();
        gemv256<NUNITS>(acc, ns_w2, ns_b2, sh, NUNITS, j);

        // ---- state update (masked) ----
#pragma unroll
        for (int g = 0; g < G; g++) {
            float nsv  = acc[g];
            float m    = smask[g];
            float yend = sy[g * LATENT + j], ytv = syt[g * LATENT + j];
            float ny   = (1.f - u[g])  * nsv + u[g]  * yend;
            float nyt  = (1.f - ut[g]) * nsv + ut[g] * ytv;
            sy [g * LATENT + j] = m * ny  + (1.f - m) * yend;
            syt[g * LATENT + j] = m * nyt + (1.f - m) * ytv;
        }
        // top-of-loop sync protects these writes
    }

    __syncthreads();
#pragma unroll
    for (int g = 0; g < G; g++)
        out_prev[(size_t)(tb + g) * LATENT + j] = sy[g * LATENT + j];
}

extern "C" void kernel_launch(void* const* d_in, const int* in_sizes, int n_in,
                              void* d_out, int out_size) {
    const float* data   = (const float*)d_in[0];
    const float* ts     = (const float*)d_in[1];
    const float* ug_w1  = (const float*)d_in[2];
    const float* ug_b1  = (const float*)d_in[3];
    const float* ug_w2  = (const float*)d_in[4];
    const float* ug_b2  = (const float*)d_in[5];
    const float* ugt_w1 = (const float*)d_in[6];
    const float* ugt_b1 = (const float*)d_in[7];
    const float* ugt_w2 = (const float*)d_in[8];
    const float* ugt_b2 = (const float*)d_in[9];
    const float* rg_w1  = (const float*)d_in[10];
    const float* rg_b1  = (const float*)d_in[11];
    const float* rg_w2  = (const float*)d_in[12];
    const float* rg_b2  = (const float*)d_in[13];
    // d_in[14..17] = rgt_* : unused by the reference
    const float* ns_w1  = (const float*)d_in[18];
    const float* ns_b1  = (const float*)d_in[19];
    const float* ns_w2  = (const float*)d_in[20];
    const float* ns_b2  = (const float*)d_in[21];
    const float* dk_w1  = (const float*)d_in[22];
    const float* dk_b1  = (const float*)d_in[23];
    const float* dk_w2  = (const float*)d_in[24];
    const float* dk_b2  = (const float*)d_in[25];
    const float* dec_w  = (const float*)d_in[26];
    const float* dec_b  = (const float*)d_in[27];

    rnn_decay_kernel<<<NBLK, 256>>>(
        data, ts,
        ug_w1, ug_b1, ug_w2, ug_b2,
        ugt_w1, ugt_b1, ugt_w2, ugt_b2,
        rg_w1, rg_b1, rg_w2, rg_b2,
        ns_w1, ns_b1, ns_w2, ns_b2,
        dk_w1, dk_b1, dk_w2, dk_b2,
        dec_w, dec_b,
        (float*)d_out);
}

// round 2
// speedup vs baseline: 2.3302x; 2.3302x over previous
#include <cuda_runtime.h>
#include <cuda_bf16.h>
#include <math.h>

#define NTRAJ  256
#define NTP    512
#define LATENT 256
#define INPUT  128
#define NUNITS 256
#define GIN    (LATENT + INPUT)   // 384
#define DEC_OUT 128
#define NSTEP  (NTP - 1)          // 511

#define G     4                   // trajectories per block
#define NBLK  (NTRAJ / G)         // 64 blocks

typedef unsigned long long u64;

union F2U { float2 f; u64 u; };

__device__ __forceinline__ u64 ffma2(u64 a, u64 b, u64 c) {
    u64 d;
    asm("fma.rn.f32x2 %0, %1, %2, %3;" : "=l"(d) : "l"(a), "l"(b), "l"(c));
    return d;
}

__device__ __forceinline__ float sigmoidf_(float x) { return 1.f / (1.f + expf(-x)); }

// ---------------------------------------------------------------------------
// Packed weights: float4 along k, i.e. W4[k4][j] = (W[4k4][j], W[4k4+1][j],
// W[4k4+2][j], W[4k4+3][j]) stored as ulonglong2 (.x = k-pair 0, .y = k-pair 1).
// ---------------------------------------------------------------------------
// offsets in ulonglong2 units (1 elem = 4 floats)
#define SZ_M384 (96 * 256)    // 384x256 matrix
#define SZ_M256 (64 * 256)    // 256x256 matrix
#define SZ_DEC  (64 * 128)    // 256x128 matrix
#define OFF_UG1  0
#define OFF_UGT1 (OFF_UG1  + SZ_M384)
#define OFF_RG1  (OFF_UGT1 + SZ_M384)
#define OFF_NS1  (OFF_RG1  + SZ_M384)
#define OFF_UG2  (OFF_NS1  + SZ_M384)
#define OFF_UGT2 (OFF_UG2  + SZ_M256)
#define OFF_RG2  (OFF_UGT2 + SZ_M256)
#define OFF_NS2  (OFF_RG2  + SZ_M256)
#define OFF_DK1  (OFF_NS2  + SZ_M256)
#define OFF_DEC  (OFF_DK1  + SZ_M256)
#define WP_TOTAL (OFF_DEC  + SZ_DEC)   // 188416

__device__ ulonglong2 g_wp[WP_TOTAL];
__device__ float g_zeros[256];           // stays zero (zero-initialized)

__global__ void pack_kernel(
    const float* ug1, const float* ugt1, const float* rg1, const float* ns1,
    const float* ug2, const float* ugt2, const float* rg2, const float* ns2,
    const float* dk1, const float* decw)
{
    const float* srcs[10] = {ug1, ugt1, rg1, ns1, ug2, ugt2, rg2, ns2, dk1, decw};
    const int offs[11] = {OFF_UG1, OFF_UGT1, OFF_RG1, OFF_NS1, OFF_UG2, OFF_UGT2,
                          OFF_RG2, OFF_NS2, OFF_DK1, OFF_DEC, WP_TOTAL};
    const int Ns[10] = {256,256,256,256,256,256,256,256,256,128};

    int idx = blockIdx.x * blockDim.x + threadIdx.x;
    if (idx >= WP_TOTAL) return;
    int m = 0;
    while (idx >= offs[m + 1]) m++;
    int local = idx - offs[m];
    int N = Ns[m];
    int k4 = local / N, j = local % N;
    const float* S = srcs[m];
    F2U lo, hi;
    lo.f = make_float2(S[(4 * k4 + 0) * N + j], S[(4 * k4 + 1) * N + j]);
    hi.f = make_float2(S[(4 * k4 + 2) * N + j], S[(4 * k4 + 3) * N + j]);
    g_wp[idx] = make_ulonglong2(lo.u, hi.u);
}

// ---------------------------------------------------------------------------
// Register-pipelined packed GEMV.
// K2 = number of k-pairs; NG matrices sharing the same activation input;
// N = output width (thread j computes output j for all G trajectories).
// acc lanes hold even-k / odd-k partial sums; combined at the end.
// ---------------------------------------------------------------------------
template <int K2, int NG, int N>
__device__ __forceinline__ void gemv_p(
    float (&res)[NG][G],
    const ulonglong2* const (&Wv)[NG],
    const float* const (&bv)[NG],
    const float* act, int astride, int j)
{
    constexpr int K4 = K2 / 2;   // ulonglong2 rows
    constexpr int CU = 2;        // k4 per chunk
    constexpr int CH = K4 / CU;  // chunks (even for all our sizes)

    u64 acc[NG][G];
#pragma unroll
    for (int ng = 0; ng < NG; ng++) {
        F2U b; b.f = make_float2(bv[ng][j], 0.f);
#pragma unroll
        for (int g = 0; g < G; g++) acc[ng][g] = (g == 0) ? b.u : 0ull;
    }
    // bias only in g==0 lane? No -- bias needed per (ng,g). Put it in all:
#pragma unroll
    for (int ng = 0; ng < NG; ng++) {
        F2U b; b.f = make_float2(bv[ng][j], 0.f);
#pragma unroll
        for (int g = 0; g < G; g++) acc[ng][g] = b.u;
    }

    ulonglong2 wA[NG][CU], wB[NG][CU];

    auto LD = [&](ulonglong2 (&w)[NG][CU], int c) {
#pragma unroll
        for (int ng = 0; ng < NG; ng++)
#pragma unroll
            for (int cu = 0; cu < CU; cu++)
                w[ng][cu] = Wv[ng][(c * CU + cu) * N + j];
    };
    auto CP = [&](ulonglong2 (&w)[NG][CU], int c) {
#pragma unroll
        for (int cu = 0; cu < CU; cu++) {
            int k4 = c * CU + cu;
            u64 a0[G], a1[G];
#pragma unroll
            for (int g = 0; g < G; g++) {
                ulonglong2 av = *(const ulonglong2*)(act + g * astride + 4 * k4);
                a0[g] = av.x; a1[g] = av.y;
            }
#pragma unroll
            for (int ng = 0; ng < NG; ng++) {
#pragma unroll
                for (int g = 0; g < G; g++) {
                    acc[ng][g] = ffma2(a0[g], w[ng][cu].x, acc[ng][g]);
                    acc[ng][g] = ffma2(a1[g], w[ng][cu].y, acc[ng][g]);
                }
            }
        }
    };

    LD(wA, 0);
#pragma unroll 1
    for (int cc = 0; cc < CH / 2; cc++) {
        LD(wB, 2 * cc + 1);
        CP(wA, 2 * cc);
        if (cc + 1 < CH / 2) LD(wA, 2 * cc + 2);
        CP(wB, 2 * cc + 1);
    }

#pragma unroll
    for (int ng = 0; ng < NG; ng++)
#pragma unroll
        for (int g = 0; g < G; g++) {
            F2U r; r.u = acc[ng][g];
            res[ng][g] = r.f.x + r.f.y;
        }
}

__global__ __launch_bounds__(256, 1)
void rnn_decay_kernel(
    const float* __restrict__ data, const float* __restrict__ ts,
    const float* __restrict__ ug_b1,  const float* __restrict__ ug_b2,
    const float* __restrict__ ugt_b1, const float* __restrict__ ugt_b2,
    const float* __restrict__ rg_b1,  const float* __restrict__ rg_b2,
    const float* __restrict__ ns_b1,  const float* __restrict__ ns_b2,
    const float* __restrict__ dk_b1,  const float* __restrict__ dk_w2,
    const float* __restrict__ dk_b2,  const float* __restrict__ dec_b,
    float* __restrict__ out)
{
    __shared__ __align__(16) float sy [G * LATENT];
    __shared__ __align__(16) float syt[G * LATENT];
    __shared__ __align__(16) float syc[G * GIN];
    __shared__ __align__(16) float shh0[G * NUNITS];
    __shared__ __align__(16) float shh1[G * NUNITS];
    __shared__ __align__(16) float shh2[G * NUNITS];
    __shared__ __align__(16) float spart[2 * G * 128];
    __shared__ float sdt[G], sdecay[G], smask[G];
    __shared__ float sred[8][G];

    const int j    = threadIdx.x;
    const int tb   = blockIdx.x * G;
    const int lane = j & 31, warp = j >> 5;

    const ulonglong2* WP = g_wp;

    float* out_prev = out;
    float* out_vol  = out + (size_t)NTRAJ * LATENT;
    float* out_dts  = out + (size_t)NTRAJ * LATENT + (size_t)NTRAJ * NSTEP * DEC_OUT;

#pragma unroll
    for (int g = 0; g < G; g++) { sy[g * LATENT + j] = 0.f; syt[g * LATENT + j] = 0.f; }

    for (int t = 0; t < NTP; t++) {
        __syncthreads();

        // ---- setup: xh -> syc tail, mask, dt ----
        if (j < INPUT) {
#pragma unroll
            for (int g = 0; g < G; g++)
                syc[g * GIN + LATENT + j] =
                    data[((size_t)(tb + g) * NTP + t) * (2 * INPUT) + j];
        }
        if (warp < G) {
            const float* xp = data + ((size_t)(tb + warp) * NTP + t) * (2 * INPUT) + INPUT;
            float s = xp[lane] + xp[lane + 32] + xp[lane + 64] + xp[lane + 96];
#pragma unroll
            for (int off = 16; off; off >>= 1) s += __shfl_xor_sync(0xffffffffu, s, off);
            if (lane == 0) smask[warp] = (s > 0.f) ? 1.f : 0.f;
        }
        if (j < G && t > 0) {
            float d = ts[(size_t)(tb + j) * NTP + t] - ts[(size_t)(tb + j) * NTP + t - 1];
            sdt[j] = d;
            out_dts[(size_t)(tb + j) * NSTEP + (t - 1)] = d;
        }
        __syncthreads();

        if (t > 0) {
            // ---- decay layer1: relu(y @ dk_w1 + b1) ----
            {
                const ulonglong2* Wd[1] = { WP + OFF_DK1 };
                const float* bd[1] = { dk_b1 };
                float r1[1][G];
                gemv_p<128, 1, 256>(r1, Wd, bd, sy, LATENT, j);
#pragma unroll
                for (int g = 0; g < G; g++) shh0[g * NUNITS + j] = fmaxf(r1[0][g], 0.f);
            }
            __syncthreads();
            // ---- decay layer2: 256 -> 1 reduce ----
            {
                float v[G];
                float w2v = dk_w2[j];
#pragma unroll
                for (int g = 0; g < G; g++) v[g] = shh0[g * NUNITS + j] * w2v;
#pragma unroll
                for (int off = 16; off; off >>= 1)
#pragma unroll
                    for (int g = 0; g < G; g++) v[g] += __shfl_xor_sync(0xffffffffu, v[g], off);
                if (lane == 0)
#pragma unroll
                    for (int g = 0; g < G; g++) sred[warp][g] = v[g];
            }
            __syncthreads();
            if (j < G) {
                float s = dk_b2[0];
#pragma unroll
                for (int w = 0; w < 8; w++) s += sred[w][j];
                sdecay[j] = fmaxf(s, 0.f);
            }
            __syncthreads();

            // ---- elementwise decay: mean_ydec -> shh0, y_end -> sy & syc head ----
#pragma unroll
            for (int g = 0; g < G; g++) {
                float d  = sdecay[g] * sdt[g];
                float e1 = expf(-0.5f * d);
                float e2 = expf(-d);
                float yv = sy[g * LATENT + j], ytv = syt[g * LATENT + j];
                float df = yv - ytv;
                shh0[g * NUNITS + j] = ytv + df * (0.5f * (1.f + e1));
                float yend = ytv + df * e2;
                sy[g * LATENT + j] = yend;
                syc[g * GIN + j]   = yend;
            }
            __syncthreads();

            // ---- vol decoder: split-K across thread halves ----
            {
                int jd = j & 127, half = j >> 7;
                const ulonglong2* Wd[1] = { WP + OFF_DEC + half * 32 * 128 };
                const float* bd[1] = { half ? g_zeros : dec_b };
                float r1[1][G];
                gemv_p<64, 1, 128>(r1, Wd, bd, shh0 + half * 128, NUNITS, jd);
#pragma unroll
                for (int g = 0; g < G; g++)
                    spart[(half * G + g) * 128 + jd] = r1[0][g];
            }
            __syncthreads();
            if (j < 128) {
#pragma unroll
                for (int g = 0; g < G; g++)
                    out_vol[((size_t)(tb + g) * NSTEP + (t - 1)) * DEC_OUT + j] =
                        spart[g * 128 + j] + spart[(G + g) * 128 + j];
            }
        } else {
#pragma unroll
            for (int g = 0; g < G; g++) syc[g * GIN + j] = 0.f;
        }
        __syncthreads();

        // ---- fused gate layer1: ug/ugt/rg share input yc ----
        {
            const ulonglong2* Wg[3] = { WP + OFF_UG1, WP + OFF_UGT1, WP + OFF_RG1 };
            const float* bg[3] = { ug_b1, ugt_b1, rg_b1 };
            float r3[3][G];
            gemv_p<192, 3, 256>(r3, Wg, bg, syc, GIN, j);
#pragma unroll
            for (int g = 0; g < G; g++) {
                shh0[g * NUNITS + j] = tanhf(r3[0][g]);
                shh1[g * NUNITS + j] = tanhf(r3[1][g]);
                shh2[g * NUNITS + j] = tanhf(r3[2][g]);
            }
        }
        __syncthreads();

        float u[G], ut[G];
        {
            const ulonglong2* Wg[1] = { WP + OFF_UG2 };
            const float* bg[1] = { ug_b2 };
            float r1[1][G];
            gemv_p<128, 1, 256>(r1, Wg, bg, shh0, NUNITS, j);
#pragma unroll
            for (int g = 0; g < G; g++) u[g] = sigmoidf_(r1[0][g]);
        }
        {
            const ulonglong2* Wg[1] = { WP + OFF_UGT2 };
            const float* bg[1] = { ugt_b2 };
            float r1[1][G];
            gemv_p<128, 1, 256>(r1, Wg, bg, shh1, NUNITS, j);
#pragma unroll
            for (int g = 0; g < G; g++) ut[g] = sigmoidf_(r1[0][g]);
        }
        {
            const ulonglong2* Wg[1] = { WP + OFF_RG2 };
            const float* bg[1] = { rg_b2 };
            float r1[1][G];
            gemv_p<128, 1, 256>(r1, Wg, bg, shh2, NUNITS, j);
#pragma unroll
            for (int g = 0; g < G; g++) syc[g * GIN + j] *= sigmoidf_(r1[0][g]);
        }
        __syncthreads();

        // ---- new_state layer1 ----
        {
            const ulonglong2* Wg[1] = { WP + OFF_NS1 };
            const float* bg[1] = { ns_b1 };
            float r1[1][G];
            gemv_p<192, 1, 256>(r1, Wg, bg, syc, GIN, j);
#pragma unroll
            for (int g = 0; g < G; g++) shh0[g * NUNITS + j] = tanhf(r1[0][g]);
        }
        __syncthreads();
        // ---- new_state layer2 + masked update ----
        {
            const ulonglong2* Wg[1] = { WP + OFF_NS2 };
            const float* bg[1] = { ns_b2 };
            float r1[1][G];
            gemv_p<128, 1, 256>(r1, Wg, bg, shh0, NUNITS, j);
#pragma unroll
            for (int g = 0; g < G; g++) {
                float nsv  = r1[0][g];
                float m    = smask[g];
                float yend = sy[g * LATENT + j], ytv = syt[g * LATENT + j];
                float ny   = (1.f - u[g])  * nsv + u[g]  * yend;
                float nyt  = (1.f - ut[g]) * nsv + ut[g] * ytv;
                sy [g * LATENT + j] = m * ny  + (1.f - m) * yend;
                syt[g * LATENT + j] = m * nyt + (1.f - m) * ytv;
            }
        }
    }

    __syncthreads();
#pragma unroll
    for (int g = 0; g < G; g++)
        out_prev[(size_t)(tb + g) * LATENT + j] = sy[g * LATENT + j];
}

extern "C" void kernel_launch(void* const* d_in, const int* in_sizes, int n_in,
                              void* d_out, int out_size) {
    const float* data   = (const float*)d_in[0];
    const float* ts     = (const float*)d_in[1];
    const float* ug_w1  = (const float*)d_in[2];
    const float* ug_b1  = (const float*)d_in[3];
    const float* ug_w2  = (const float*)d_in[4];
    const float* ug_b2  = (const float*)d_in[5];
    const float* ugt_w1 = (const float*)d_in[6];
    const float* ugt_b1 = (const float*)d_in[7];
    const float* ugt_w2 = (const float*)d_in[8];
    const float* ugt_b2 = (const float*)d_in[9];
    const float* rg_w1  = (const float*)d_in[10];
    const float* rg_b1  = (const float*)d_in[11];
    const float* rg_w2  = (const float*)d_in[12];
    const float* rg_b2  = (const float*)d_in[13];
    // d_in[14..17] = rgt_* : unused by the reference
    const float* ns_w1  = (const float*)d_in[18];
    const float* ns_b1  = (const float*)d_in[19];
    const float* ns_w2  = (const float*)d_in[20];
    const float* ns_b2  = (const float*)d_in[21];
    const float* dk_w1  = (const float*)d_in[22];
    const float* dk_b1  = (const float*)d_in[23];
    const float* dk_w2  = (const float*)d_in[24];
    const float* dk_b2  = (const float*)d_in[25];
    const float* dec_w  = (const float*)d_in[26];
    const float* dec_b  = (const float*)d_in[27];

    pack_kernel<<<(WP_TOTAL + 255) / 256, 256>>>(
        ug_w1, ugt_w1, rg_w1, ns_w1, ug_w2, ugt_w2, rg_w2, ns_w2, dk_w1, dec_w);

    rnn_decay_kernel<<<NBLK, 256>>>(
        data, ts,
        ug_b1, ug_b2, ugt_b1, ugt_b2, rg_b1, rg_b2,
        ns_b1, ns_b2, dk_b1, dk_w2, dk_b2, dec_b,
        (float*)d_out);
}

// round 3
// speedup vs baseline: 2.4253x; 1.0408x over previous
#include <cuda_runtime.h>
#include <cuda_bf16.h>
#include <math.h>

#define NTRAJ  256
#define NTP    512
#define LATENT 256
#define INPUT  128
#define NUNITS 256
#define GIN    (LATENT + INPUT)   // 384
#define DEC_OUT 128
#define NSTEP  (NTP - 1)          // 511

#define G     4                   // trajectories per block
#define NBLK  (NTRAJ / G)         // 64 blocks
#define THREADS 512               // split-K x2 (x4 for decoder)

typedef unsigned long long u64;

union F2U { float2 f; u64 u; };

__device__ __forceinline__ u64 ffma2(u64 a, u64 b, u64 c) {
    u64 d;
    asm("fma.rn.f32x2 %0, %1, %2, %3;" : "=l"(d) : "l"(a), "l"(b), "l"(c));
    return d;
}

__device__ __forceinline__ float lanesum(u64 v) {
    F2U r; r.u = v; return r.f.x + r.f.y;
}

__device__ __forceinline__ float sigmoidf_(float x) { return 1.f / (1.f + expf(-x)); }

// ---------------------------------------------------------------------------
// Packed weights: float4 along k: W4[k4][j] = W[4k4..4k4+3][j], as ulonglong2.
// ---------------------------------------------------------------------------
#define SZ_M384 (96 * 256)
#define SZ_M256 (64 * 256)
#define SZ_DEC  (64 * 128)
#define OFF_UG1  0
#define OFF_UGT1 (OFF_UG1  + SZ_M384)
#define OFF_RG1  (OFF_UGT1 + SZ_M384)
#define OFF_NS1  (OFF_RG1  + SZ_M384)
#define OFF_UG2  (OFF_NS1  + SZ_M384)
#define OFF_UGT2 (OFF_UG2  + SZ_M256)
#define OFF_RG2  (OFF_UGT2 + SZ_M256)
#define OFF_NS2  (OFF_RG2  + SZ_M256)
#define OFF_DK1  (OFF_NS2  + SZ_M256)
#define OFF_DEC  (OFF_DK1  + SZ_M256)
#define WP_TOTAL (OFF_DEC  + SZ_DEC)

__device__ ulonglong2 g_wp[WP_TOTAL];

__global__ void pack_kernel(
    const float* ug1, const float* ugt1, const float* rg1, const float* ns1,
    const float* ug2, const float* ugt2, const float* rg2, const float* ns2,
    const float* dk1, const float* decw)
{
    const float* srcs[10] = {ug1, ugt1, rg1, ns1, ug2, ugt2, rg2, ns2, dk1, decw};
    const int offs[11] = {OFF_UG1, OFF_UGT1, OFF_RG1, OFF_NS1, OFF_UG2, OFF_UGT2,
                          OFF_RG2, OFF_NS2, OFF_DK1, OFF_DEC, WP_TOTAL};
    const int Ns[10] = {256,256,256,256,256,256,256,256,256,128};

    int idx = blockIdx.x * blockDim.x + threadIdx.x;
    if (idx >= WP_TOTAL) return;
    int m = 0;
    while (idx >= offs[m + 1]) m++;
    int local = idx - offs[m];
    int N = Ns[m];
    int k4 = local / N, j = local % N;
    const float* S = srcs[m];
    F2U lo, hi;
    lo.f = make_float2(S[(4 * k4 + 0) * N + j], S[(4 * k4 + 1) * N + j]);
    hi.f = make_float2(S[(4 * k4 + 2) * N + j], S[(4 * k4 + 3) * N + j]);
    g_wp[idx] = make_ulonglong2(lo.u, hi.u);
}

// ---------------------------------------------------------------------------
// Partial packed GEMV over one k-slice (no bias; caller adds at combine).
// K2H = k-pairs in this slice, NG matrices sharing one activation input,
// N = output width, CU = k4-rows per prefetch chunk.
// ---------------------------------------------------------------------------
template <int K2H, int NG, int N, int CU>
__device__ __forceinline__ void gemv_part(
    float (&res)[NG][G],
    const ulonglong2* const (&Wv)[NG],
    const float* act, int astride, int j)
{
    constexpr int K4 = K2H / 2;
    constexpr int CH = K4 / CU;
    static_assert(CH % 2 == 0, "chunks must be even");

    u64 acc[NG][G];
#pragma unroll
    for (int ng = 0; ng < NG; ng++)
#pragma unroll
        for (int g = 0; g < G; g++) acc[ng][g] = 0ull;

    ulonglong2 wA[NG][CU], wB[NG][CU];

    auto LD = [&](ulonglong2 (&w)[NG][CU], int c) {
#pragma unroll
        for (int ng = 0; ng < NG; ng++)
#pragma unroll
            for (int cu = 0; cu < CU; cu++)
                w[ng][cu] = Wv[ng][(c * CU + cu) * N + j];
    };
    auto CP = [&](ulonglong2 (&w)[NG][CU], int c) {
#pragma unroll
        for (int cu = 0; cu < CU; cu++) {
            int k4 = c * CU + cu;
            u64 a0[G], a1[G];
#pragma unroll
            for (int g = 0; g < G; g++) {
                ulonglong2 av = *(const ulonglong2*)(act + g * astride + 4 * k4);
                a0[g] = av.x; a1[g] = av.y;
            }
#pragma unroll
            for (int ng = 0; ng < NG; ng++)
#pragma unroll
                for (int g = 0; g < G; g++) {
                    acc[ng][g] = ffma2(a0[g], w[ng][cu].x, acc[ng][g]);
                    acc[ng][g] = ffma2(a1[g], w[ng][cu].y, acc[ng][g]);
                }
        }
    };

    LD(wA, 0);
#pragma unroll 1
    for (int cc = 0; cc < CH / 2; cc++) {
        LD(wB, 2 * cc + 1);
        CP(wA, 2 * cc);
        if (cc + 1 < CH / 2) LD(wA, 2 * cc + 2);
        CP(wB, 2 * cc + 1);
    }

#pragma unroll
    for (int ng = 0; ng < NG; ng++)
#pragma unroll
        for (int g = 0; g < G; g++) res[ng][g] = lanesum(acc[ng][g]);
}

__global__ __launch_bounds__(THREADS, 1)
void rnn_decay_kernel(
    const float* __restrict__ data, const float* __restrict__ ts,
    const float* __restrict__ ug_b1,  const float* __restrict__ ug_b2,
    const float* __restrict__ ugt_b1, const float* __restrict__ ugt_b2,
    const float* __restrict__ rg_b1,  const float* __restrict__ rg_b2,
    const float* __restrict__ ns_b1,  const float* __restrict__ ns_b2,
    const float* __restrict__ dk_b1,  const float* __restrict__ dk_w2,
    const float* __restrict__ dk_b2,  const float* __restrict__ dec_b,
    float* __restrict__ out)
{
    __shared__ __align__(16) float sy [G * LATENT];
    __shared__ __align__(16) float syt[G * LATENT];
    __shared__ __align__(16) float syc[G * GIN];
    __shared__ __align__(16) float shh0[G * NUNITS];
    __shared__ __align__(16) float shh1[G * NUNITS];
    __shared__ __align__(16) float shh2[G * NUNITS];
    __shared__ __align__(16) float spart[3][G][256];
    __shared__ float sdt[G], sdecay[G], smask[G];
    __shared__ float sred[8][G];

    const int tid  = threadIdx.x;
    const int j    = tid & 255;          // output unit for 256-wide gemvs
    const int half = tid >> 8;           // k-half
    const int lane = tid & 31, warp = tid >> 5;
    const int tb   = blockIdx.x * G;

    const ulonglong2* WP = g_wp;

    float* out_prev = out;
    float* out_vol  = out + (size_t)NTRAJ * LATENT;
    float* out_dts  = out + (size_t)NTRAJ * LATENT + (size_t)NTRAJ * NSTEP * DEC_OUT;

    for (int i = tid; i < G * LATENT; i += THREADS) { sy[i] = 0.f; syt[i] = 0.f; }

    for (int t = 0; t < NTP; t++) {
        __syncthreads();

        // ---- setup: xh -> syc tail (512 threads = G*128 elems), mask, dt ----
        {
            int g = tid >> 7, jj = tid & 127;
            syc[g * GIN + LATENT + jj] =
                data[((size_t)(tb + g) * NTP + t) * (2 * INPUT) + jj];
        }
        if (warp < G) {
            const float* xp = data + ((size_t)(tb + warp) * NTP + t) * (2 * INPUT) + INPUT;
            float s = xp[lane] + xp[lane + 32] + xp[lane + 64] + xp[lane + 96];
#pragma unroll
            for (int off = 16; off; off >>= 1) s += __shfl_xor_sync(0xffffffffu, s, off);
            if (lane == 0) smask[warp] = (s > 0.f) ? 1.f : 0.f;
        }
        if (tid < G && t > 0) {
            float d = ts[(size_t)(tb + tid) * NTP + t] - ts[(size_t)(tb + tid) * NTP + t - 1];
            sdt[tid] = d;
            out_dts[(size_t)(tb + tid) * NSTEP + (t - 1)] = d;
        }
        __syncthreads();

        if (t > 0) {
            // ---- decay layer1 (256->256), split-K x2 ----
            {
                const ulonglong2* Wd[1] = { WP + OFF_DK1 + half * 32 * 256 };
                float p[1][G];
                gemv_part<64, 1, 256, 2>(p, Wd, sy + half * 128, LATENT, j);
                if (half) {
#pragma unroll
                    for (int g = 0; g < G; g++) spart[0][g][j] = p[0][g];
                }
                __syncthreads();
                if (!half) {
#pragma unroll
                    for (int g = 0; g < G; g++)
                        shh0[g * NUNITS + j] = fmaxf(p[0][g] + spart[0][g][j] + dk_b1[j], 0.f);
                }
                __syncthreads();
            }
            // ---- decay layer2: 256 -> 1 (warps 0..7 = half 0) ----
            if (!half) {
                float v[G];
                float w2v = dk_w2[j];
#pragma unroll
                for (int g = 0; g < G; g++) v[g] = shh0[g * NUNITS + j] * w2v;
#pragma unroll
                for (int off = 16; off; off >>= 1)
#pragma unroll
                    for (int g = 0; g < G; g++) v[g] += __shfl_xor_sync(0xffffffffu, v[g], off);
                if (lane == 0)
#pragma unroll
                    for (int g = 0; g < G; g++) sred[warp][g] = v[g];
            }
            __syncthreads();
            if (tid < G) {
                float s = dk_b2[0];
#pragma unroll
                for (int w = 0; w < 8; w++) s += sred[w][tid];
                sdecay[tid] = fmaxf(s, 0.f);
            }
            __syncthreads();

            // ---- elementwise decay: mean_ydec -> shh0, y_end -> sy & syc head ----
            if (!half) {
#pragma unroll
                for (int g = 0; g < G; g++) {
                    float d  = sdecay[g] * sdt[g];
                    float e1 = expf(-0.5f * d);
                    float e2 = expf(-d);
                    float yv = sy[g * LATENT + j], ytv = syt[g * LATENT + j];
                    float df = yv - ytv;
                    shh0[g * NUNITS + j] = ytv + df * (0.5f * (1.f + e1));
                    float yend = ytv + df * e2;
                    sy[g * LATENT + j] = yend;
                    syc[g * GIN + j]   = yend;
                }
            }
            __syncthreads();

            // ---- vol decoder (256->128), split-K x4 ----
            {
                int q = tid >> 7, jd = tid & 127;
                const ulonglong2* Wd[1] = { WP + OFF_DEC + q * 16 * 128 };
                float p[1][G];
                gemv_part<32, 1, 128, 2>(p, Wd, shh0 + q * 64, NUNITS, jd);
                if (q) {
#pragma unroll
                    for (int g = 0; g < G; g++) spart[q - 1][g][jd] = p[0][g];
                }
                __syncthreads();
                if (!q) {
#pragma unroll
                    for (int g = 0; g < G; g++)
                        out_vol[((size_t)(tb + g) * NSTEP + (t - 1)) * DEC_OUT + jd] =
                            p[0][g] + spart[0][g][jd] + spart[1][g][jd] + spart[2][g][jd]
                            + dec_b[jd];
                }
            }
        } else {
            if (!half) {
#pragma unroll
                for (int g = 0; g < G; g++) syc[g * GIN + j] = 0.f;
            }
        }
        __syncthreads();

        // ---- fused gate layer1: ug/ugt/rg share input yc (384->256 x3) ----
        {
            const ulonglong2* Wg[3] = { WP + OFF_UG1  + half * 48 * 256,
                                        WP + OFF_UGT1 + half * 48 * 256,
                                        WP + OFF_RG1  + half * 48 * 256 };
            float p[3][G];
            gemv_part<96, 3, 256, 1>(p, Wg, syc + half * 192, GIN, j);
            if (half) {
#pragma unroll
                for (int ng = 0; ng < 3; ng++)
#pragma unroll
                    for (int g = 0; g < G; g++) spart[ng][g][j] = p[ng][g];
            }
            __syncthreads();
            if (!half) {
#pragma unroll
                for (int g = 0; g < G; g++) {
                    shh0[g * NUNITS + j] = tanhf(p[0][g] + spart[0][g][j] + ug_b1[j]);
                    shh1[g * NUNITS + j] = tanhf(p[1][g] + spart[1][g][j] + ugt_b1[j]);
                    shh2[g * NUNITS + j] = tanhf(p[2][g] + spart[2][g][j] + rg_b1[j]);
                }
            }
            __syncthreads();
        }

        // ---- gate layer2 x3 (256->256 each), partials batched, one combine ----
        float u[G], ut[G];
        {
            const ulonglong2* W0[1] = { WP + OFF_UG2  + half * 32 * 256 };
            const ulonglong2* W1[1] = { WP + OFF_UGT2 + half * 32 * 256 };
            const ulonglong2* W2[1] = { WP + OFF_RG2  + half * 32 * 256 };
            float p0[1][G], p1[1][G], p2[1][G];
            gemv_part<64, 1, 256, 2>(p0, W0, shh0 + half * 128, NUNITS, j);
            gemv_part<64, 1, 256, 2>(p1, W1, shh1 + half * 128, NUNITS, j);
            gemv_part<64, 1, 256, 2>(p2, W2, shh2 + half * 128, NUNITS, j);
            if (half) {
#pragma unroll
                for (int g = 0; g < G; g++) {
                    spart[0][g][j] = p0[0][g];
                    spart[1][g][j] = p1[0][g];
                    spart[2][g][j] = p2[0][g];
                }
            }
            __syncthreads();
            if (!half) {
#pragma unroll
                for (int g = 0; g < G; g++) {
                    u[g]  = sigmoidf_(p0[0][g] + spart[0][g][j] + ug_b2[j]);
                    ut[g] = sigmoidf_(p1[0][g] + spart[1][g][j] + ugt_b2[j]);
                    syc[g * GIN + j] *= sigmoidf_(p2[0][g] + spart[2][g][j] + rg_b2[j]);
                }
            }
            __syncthreads();
        }

        // ---- new_state layer1 (384->256) ----
        {
            const ulonglong2* Wg[1] = { WP + OFF_NS1 + half * 48 * 256 };
            float p[1][G];
            gemv_part<96, 1, 256, 2>(p, Wg, syc + half * 192, GIN, j);
            if (half) {
#pragma unroll
                for (int g = 0; g < G; g++) spart[0][g][j] = p[0][g];
            }
            __syncthreads();
            if (!half) {
#pragma unroll
                for (int g = 0; g < G; g++)
                    shh0[g * NUNITS + j] = tanhf(p[0][g] + spart[0][g][j] + ns_b1[j]);
            }
            __syncthreads();
        }

        // ---- new_state layer2 (256->256) + masked state update ----
        {
            const ulonglong2* Wg[1] = { WP + OFF_NS2 + half * 32 * 256 };
            float p[1][G];
            gemv_part<64, 1, 256, 2>(p, Wg, shh0 + half * 128, NUNITS, j);
            if (half) {
#pragma unroll
                for (int g = 0; g < G; g++) spart[0][g][j] = p[0][g];
            }
            __syncthreads();
            if (!half) {
#pragma unroll
                for (int g = 0; g < G; g++) {
                    float nsv  = p[0][g] + spart[0][g][j] + ns_b2[j];
                    float m    = smask[g];
                    float yend = sy[g * LATENT + j], ytv = syt[g * LATENT + j];
                    float ny   = (1.f - u[g])  * nsv + u[g]  * yend;
                    float nyt  = (1.f - ut[g]) * nsv + ut[g] * ytv;
                    sy [g * LATENT + j] = m * ny  + (1.f - m) * yend;
                    syt[g * LATENT + j] = m * nyt + (1.f - m) * ytv;
                }
            }
        }
        // top-of-loop sync protects sy/syt writes
    }

    __syncthreads();
    if (!half) {
#pragma unroll
        for (int g = 0; g < G; g++)
            out_prev[(size_t)(tb + g) * LATENT + j] = sy[g * LATENT + j];
    }
}

extern "C" void kernel_launch(void* const* d_in, const int* in_sizes, int n_in,
                              void* d_out, int out_size) {
    const float* data   = (const float*)d_in[0];
    const float* ts     = (const float*)d_in[1];
    const float* ug_w1  = (const float*)d_in[2];
    const float* ug_b1  = (const float*)d_in[3];
    const float* ug_w2  = (const float*)d_in[4];
    const float* ug_b2  = (const float*)d_in[5];
    const float* ugt_w1 = (const float*)d_in[6];
    const float* ugt_b1 = (const float*)d_in[7];
    const float* ugt_w2 = (const float*)d_in[8];
    const float* ugt_b2 = (const float*)d_in[9];
    const float* rg_w1  = (const float*)d_in[10];
    const float* rg_b1  = (const float*)d_in[11];
    const float* rg_w2  = (const float*)d_in[12];
    const float* rg_b2  = (const float*)d_in[13];
    // d_in[14..17] = rgt_* : unused by the reference
    const float* ns_w1  = (const float*)d_in[18];
    const float* ns_b1  = (const float*)d_in[19];
    const float* ns_w2  = (const float*)d_in[20];
    const float* ns_b2  = (const float*)d_in[21];
    const float* dk_w1  = (const float*)d_in[22];
    const float* dk_b1  = (const float*)d_in[23];
    const float* dk_w2  = (const float*)d_in[24];
    const float* dk_b2  = (const float*)d_in[25];
    const float* dec_w  = (const float*)d_in[26];
    const float* dec_b  = (const float*)d_in[27];

    pack_kernel<<<(WP_TOTAL + 255) / 256, 256>>>(
        ug_w1, ugt_w1, rg_w1, ns_w1, ug_w2, ugt_w2, rg_w2, ns_w2, dk_w1, dec_w);

    rnn_decay_kernel<<<NBLK, THREADS>>>(
        data, ts,
        ug_b1, ug_b2, ugt_b1, ugt_b2, rg_b1, rg_b2,
        ns_b1, ns_b2, dk_b1, dk_w2, dk_b2, dec_b,
        (float*)d_out);
}